// round 1
// baseline (speedup 1.0000x reference)
#include <cuda_runtime.h>

#define NN  50000
#define EE  1600000
#define FIN 128
#define HH  32
#define CC  16

// Scratch (device globals: no allocations allowed)
__device__ float g_deg[NN];
__device__ float g_dinv[NN];
__device__ float g_xws[NN * HH];   // per-row dinv-prescaled features
__device__ float g_agg[NN * HH];   // aggregation accumulator
__device__ float g_h1[NN * HH];    // layer-1 activations

// ---------------------------------------------------------------- degrees
__global__ void k_init_deg() {
    int i = blockIdx.x * blockDim.x + threadIdx.x;
    if (i < NN) g_deg[i] = 1.0f;                 // self-loop
}

__global__ void k_count_deg(const int* __restrict__ dst) {
    int e = blockIdx.x * blockDim.x + threadIdx.x;
    if (e < EE) atomicAdd(&g_deg[dst[e]], 1.0f);
}

__global__ void k_dinv() {
    int i = blockIdx.x * blockDim.x + threadIdx.x;
    if (i < NN) g_dinv[i] = rsqrtf(g_deg[i]);
}

// ---------------------------------------------------------------- GEMM1: xws = (x @ W1) * dinv[row]
// 256 threads = 8 warps, warp-per-row, W1 (16KB) + 8 x-rows (4KB) in smem.
__global__ void k_gemm1(const float* __restrict__ x, const float* __restrict__ W1) {
    __shared__ float Ws[FIN * HH];
    __shared__ float xs[8][FIN];
    int tid = threadIdx.x;
    for (int i = tid; i < FIN * HH; i += 256) Ws[i] = W1[i];
    int row0 = blockIdx.x * 8;
    for (int i = tid; i < 8 * FIN; i += 256) {
        int r = i >> 7, c = i & 127;
        int gr = row0 + r;
        xs[r][c] = (gr < NN) ? x[gr * FIN + c] : 0.0f;
    }
    __syncthreads();
    int warp = tid >> 5, lane = tid & 31;
    int row = row0 + warp;
    if (row >= NN) return;
    float acc = 0.0f;
    const float4* xs4 = (const float4*)xs[warp];
#pragma unroll
    for (int o = 0; o < 32; o++) {
        float4 xv = xs4[o];          // 16B broadcast LDS
        int k = 4 * o;
        acc += xv.x * Ws[(k + 0) * HH + lane];
        acc += xv.y * Ws[(k + 1) * HH + lane];
        acc += xv.z * Ws[(k + 2) * HH + lane];
        acc += xv.w * Ws[(k + 3) * HH + lane];
    }
    float v = acc * g_dinv[row];
    g_xws[row * HH + lane] = v;
    g_agg[row * HH + lane] = v;      // seed with self-loop contribution
}

// ---------------------------------------------------------------- edge scatter: agg[dst] += xws[src]
// 8 lanes per edge, each lane one float4, vectorized reduction.
__global__ void k_scatter(const int* __restrict__ src, const int* __restrict__ dst) {
    int idx = blockIdx.x * blockDim.x + threadIdx.x;
    if (idx >= EE * 8) return;
    int e  = idx >> 3;
    int c4 = (idx & 7) << 2;
    int s = __ldg(src + e);
    int d = __ldg(dst + e);
    float4 v = *(const float4*)(g_xws + s * HH + c4);
    float* p = g_agg + d * HH + c4;
    asm volatile("red.global.add.v4.f32 [%0], {%1,%2,%3,%4};"
                 :: "l"(p), "f"(v.x), "f"(v.y), "f"(v.z), "f"(v.w)
                 : "memory");
}

// ---------------------------------------------------------------- finalize layer1: h1 = tanh(dinv*agg + b)
__global__ void k_fin1(const float* __restrict__ b1) {
    int idx = blockIdx.x * blockDim.x + threadIdx.x;
    if (idx >= NN * 8) return;
    int node = idx >> 3, c4 = (idx & 7) << 2;
    float di = g_dinv[node];
    float4 a = *(const float4*)(g_agg + node * HH + c4);
    float4 b = *(const float4*)(b1 + c4);
    float4 h;
    h.x = tanhf(di * a.x + b.x);
    h.y = tanhf(di * a.y + b.y);
    h.z = tanhf(di * a.z + b.z);
    h.w = tanhf(di * a.w + b.w);
    *(float4*)(g_h1 + node * HH + c4) = h;
}

// ---------------------------------------------------------------- GEMM2: xws = (h1 @ W2) * dinv[row]
__global__ void k_gemm2(const float* __restrict__ W2) {
    __shared__ float Ws[HH * HH];
    int tid = threadIdx.x;
    for (int i = tid; i < HH * HH; i += 256) Ws[i] = W2[i];
    __syncthreads();
    int warp = tid >> 5, lane = tid & 31;
    int row = blockIdx.x * 8 + warp;
    if (row >= NN) return;
    float hv = g_h1[row * HH + lane];
    float acc = 0.0f;
#pragma unroll
    for (int j = 0; j < 32; j++) {
        float hj = __shfl_sync(0xffffffffu, hv, j);
        acc += hj * Ws[j * HH + lane];
    }
    float v = acc * g_dinv[row];
    g_xws[row * HH + lane] = v;
    g_agg[row * HH + lane] = v;
}

// ---------------------------------------------------------------- finalize layer2 + classifier
// h = tanh(dinv*agg + b2); out = h @ Wc + bc. Warp-per-row.
__global__ void k_fin2(const float* __restrict__ b2, const float* __restrict__ Wc,
                       const float* __restrict__ bc, float* __restrict__ out) {
    __shared__ float Wcs[HH * CC];
    int tid = threadIdx.x;
    for (int i = tid; i < HH * CC; i += 256) Wcs[i] = Wc[i];
    __syncthreads();
    int warp = tid >> 5, lane = tid & 31;
    int row = blockIdx.x * 8 + warp;
    if (row >= NN) return;
    float di = g_dinv[row];
    float h = tanhf(di * g_agg[row * HH + lane] + b2[lane]);
    out[NN * CC + row * HH + lane] = h;      // second output: h [N,32]
    int cl = lane & (CC - 1);
    float acc = bc[cl];
#pragma unroll
    for (int j = 0; j < 32; j++) {
        float hj = __shfl_sync(0xffffffffu, h, j);
        acc += hj * Wcs[j * CC + cl];
    }
    if (lane < CC) out[row * CC + lane] = acc;   // first output: out [N,16]
}

// ---------------------------------------------------------------- launch
extern "C" void kernel_launch(void* const* d_in, const int* in_sizes, int n_in,
                              void* d_out, int out_size) {
    const float* x  = (const float*)d_in[0];
    const int*   ei = (const int*)  d_in[1];
    const float* W1 = (const float*)d_in[2];
    const float* b1 = (const float*)d_in[3];
    const float* W2 = (const float*)d_in[4];
    const float* b2 = (const float*)d_in[5];
    const float* Wc = (const float*)d_in[6];
    const float* bc = (const float*)d_in[7];
    const int* src = ei;          // edge_index[0]
    const int* dst = ei + EE;     // edge_index[1]
    float* out = (float*)d_out;

    k_init_deg <<<(NN + 255) / 256, 256>>>();
    k_count_deg<<<(EE + 255) / 256, 256>>>(dst);
    k_dinv     <<<(NN + 255) / 256, 256>>>();

    k_gemm1    <<<(NN + 7) / 8, 256>>>(x, W1);
    k_scatter  <<<(EE * 8 + 255) / 256, 256>>>(src, dst);
    k_fin1     <<<(NN * 8 + 255) / 256, 256>>>(b1);

    k_gemm2    <<<(NN + 7) / 8, 256>>>(W2);
    k_scatter  <<<(EE * 8 + 255) / 256, 256>>>(src, dst);
    k_fin2     <<<(NN + 7) / 8, 256>>>(b2, Wc, bc, out);
}